// round 5
// baseline (speedup 1.0000x reference)
#include <cuda_runtime.h>
#include <cuda_bf16.h>
#include <cstdint>

// ---------------- problem constants ----------------
#define T_LEN 2048
#define DM    1024
#define NHEAD 16
#define HDIM  64
#define NB    32
#define SSEL  16
#define NEGV  (-1e30f)
#define NEGS  (-1.25e29f)

// ---------------- scratch ----------------------------------------------------
__device__ float g_q   [T_LEN * DM];
__device__ float g_k   [T_LEN * HDIM];
__device__ float g_v   [T_LEN * HDIM];
__device__ float g_g   [T_LEN * 48];
__device__ float g_kc  [NB * HDIM];
__device__ float g_vc  [NB * HDIM];
__device__ float g_ocmp[T_LEN * DM];
__device__ int   g_blk [T_LEN * SSEL];

__device__ __nv_bfloat16 g_xh [T_LEN * DM], g_xl [T_LEN * DM];
__device__ __nv_bfloat16 g_qh [T_LEN * DM], g_ql [T_LEN * DM];
__device__ __nv_bfloat16 g_ch [T_LEN * DM], g_cl [T_LEN * DM];
__device__ __nv_bfloat16 g_kh [T_LEN * HDIM], g_kl [T_LEN * HDIM];
__device__ __nv_bfloat16 g_vh [T_LEN * HDIM], g_vl [T_LEN * HDIM];
__device__ __nv_bfloat16 g_wch[1280 * DM], g_wcl[1280 * DM];   // stacked Wq|Wk|Wv|Wg|pad
__device__ __nv_bfloat16 g_woh[DM * DM],   g_wol[DM * DM];

// ================= helpers ==================================================
__device__ __forceinline__ uint32_t smem_u32(const void* p) {
    uint32_t a;
    asm("{ .reg .u64 t; cvta.to.shared.u64 t, %1; cvt.u32.u64 %0, t; }"
        : "=r"(a) : "l"(p));
    return a;
}
__device__ __forceinline__ void cp_async16(uint32_t saddr, const void* gaddr) {
    asm volatile("cp.async.cg.shared.global [%0], [%1], 16;"
                 :: "r"(saddr), "l"(gaddr));
}
__device__ __forceinline__ void cp_commit() {
    asm volatile("cp.async.commit_group;" ::: "memory");
}
__device__ __forceinline__ void cp_wait0() {
    asm volatile("cp.async.wait_group 0;" ::: "memory");
}
__device__ __forceinline__ void cp_wait1() {
    asm volatile("cp.async.wait_group 1;" ::: "memory");
}
__device__ __forceinline__ void ldsm4(uint32_t* r, uint32_t addr) {
    asm volatile("ldmatrix.sync.aligned.m8n8.x4.shared.b16 {%0,%1,%2,%3}, [%4];"
                 : "=r"(r[0]), "=r"(r[1]), "=r"(r[2]), "=r"(r[3]) : "r"(addr));
}
__device__ __forceinline__ void ldsm2(uint32_t* r, uint32_t addr) {
    asm volatile("ldmatrix.sync.aligned.m8n8.x2.shared.b16 {%0,%1}, [%2];"
                 : "=r"(r[0]), "=r"(r[1]) : "r"(addr));
}
__device__ __forceinline__ void ldsm4t(uint32_t* r, uint32_t addr) {
    asm volatile("ldmatrix.sync.aligned.m8n8.x4.trans.shared.b16 {%0,%1,%2,%3}, [%4];"
                 : "=r"(r[0]), "=r"(r[1]), "=r"(r[2]), "=r"(r[3]) : "r"(addr));
}
__device__ __forceinline__ void mma16816(float* d, const uint32_t* a, const uint32_t* b) {
    asm volatile(
        "mma.sync.aligned.m16n8k16.row.col.f32.bf16.bf16.f32 "
        "{%0,%1,%2,%3}, {%4,%5,%6,%7}, {%8,%9}, {%0,%1,%2,%3};"
        : "+f"(d[0]), "+f"(d[1]), "+f"(d[2]), "+f"(d[3])
        : "r"(a[0]), "r"(a[1]), "r"(a[2]), "r"(a[3]), "r"(b[0]), "r"(b[1]));
}
__device__ __forceinline__ void mma16808(float* d, uint32_t a0, uint32_t a1, uint32_t b0) {
    asm volatile(
        "mma.sync.aligned.m16n8k8.row.col.f32.bf16.bf16.f32 "
        "{%0,%1,%2,%3}, {%4,%5}, {%6}, {%0,%1,%2,%3};"
        : "+f"(d[0]), "+f"(d[1]), "+f"(d[2]), "+f"(d[3])
        : "r"(a0), "r"(a1), "r"(b0));
}
__device__ __forceinline__ uint32_t pack_bf16x2(float lo, float hi) {
    uint32_t r;
    asm("cvt.rn.bf16x2.f32 %0, %1, %2;" : "=r"(r) : "f"(hi), "f"(lo));
    return r;
}
__device__ __forceinline__ uint32_t pack_hi(float a, float b, __nv_bfloat16& ha, __nv_bfloat16& hb) {
    ha = __float2bfloat16(a); hb = __float2bfloat16(b);
    return (uint32_t)__bfloat16_as_ushort(ha) | ((uint32_t)__bfloat16_as_ushort(hb) << 16);
}

// ================= fp32 -> bf16 hi/lo conversion ============================
__global__ __launch_bounds__(256) void conv_hilo(const float4* __restrict__ src,
                                                 uint2* __restrict__ h,
                                                 uint2* __restrict__ l, int n4) {
    int i = blockIdx.x * 256 + threadIdx.x;
    if (i >= n4) return;
    float4 v = src[i];
    __nv_bfloat16 h0, h1, h2, h3;
    uint32_t a = pack_hi(v.x, v.y, h0, h1);
    uint32_t b = pack_hi(v.z, v.w, h2, h3);
    uint2 hv, lv;
    hv.x = a; hv.y = b;
    lv.x = pack_bf16x2(v.x - __bfloat162float(h0), v.y - __bfloat162float(h1));
    lv.y = pack_bf16x2(v.z - __bfloat162float(h2), v.w - __bfloat162float(h3));
    h[i] = hv;
    l[i] = lv;
}

// ================= tensor-core GEMM via mma.sync (bf16x3) ===================
#define TSTRIDE 80
#define TILE_BYTES (128 * TSTRIDE)
#define BUF_BYTES  (4 * TILE_BYTES)
#define GEMM_SMEM  (2 * BUF_BYTES)

// mode 0: C[r*1024+cc] = v  (plain output)
// mode 1: route columns: [0,1024)->q(+hilo), [1024,1088)->k(+hilo),
//         [1088,1152)->v(+hilo), [1152,1200)->g, else discard
__global__ __launch_bounds__(256) void gemm_mma(const __nv_bfloat16* __restrict__ Ah,
                                                const __nv_bfloat16* __restrict__ Al,
                                                const __nv_bfloat16* __restrict__ Bh,
                                                const __nv_bfloat16* __restrict__ Bl,
                                                float* __restrict__ C,
                                                int mode) {
    extern __shared__ char sm[];
    const uint32_t sbase = smem_u32(sm);
    const int tid = threadIdx.x;
    const int lane = tid & 31, wid = tid >> 5;
    const int m0 = blockIdx.y * 128;
    const int n0 = blockIdx.x * 128;
    const int wm = (wid >> 2) * 64;
    const int wn = (wid & 3) * 32;

    const __nv_bfloat16* gsrc[4] = {Ah, Al, Bh, Bl};

    float acc[4][4][4];
#pragma unroll
    for (int i = 0; i < 4; i++)
#pragma unroll
        for (int j = 0; j < 4; j++)
#pragma unroll
            for (int k = 0; k < 4; k++) acc[i][j][k] = 0.f;

    const int arow = wm + (lane & 15);
    const int akc  = (lane >> 4) << 3;
    const int brow = wn + (lane & 7) + ((lane >> 4) << 3);
    const int bkc  = ((lane >> 3) & 1) << 3;

    auto issue = [&](int c, int buf) {
#pragma unroll
        for (int T = 0; T < 4; T++) {
            const __nv_bfloat16* src = gsrc[T];
            const int rb = (T < 2) ? m0 : n0;
#pragma unroll
            for (int i = 0; i < 2; i++) {
                int idx = i * 256 + tid;
                int row = idx >> 2;
                int u   = idx & 3;
                uint32_t sa = sbase + buf * BUF_BYTES + T * TILE_BYTES + row * TSTRIDE + u * 16;
                cp_async16(sa, src + (size_t)(rb + row) * 1024 + c * 32 + u * 8);
            }
        }
        cp_commit();
    };

    issue(0, 0);

    for (int c = 0; c < 32; c++) {
        const int buf = c & 1;
        cp_wait0();
        __syncthreads();
        if (c + 1 < 32) issue(c + 1, buf ^ 1);

        const uint32_t base = sbase + buf * BUF_BYTES;
#pragma unroll
        for (int ks = 0; ks < 2; ks++) {
            uint32_t ah[4][4], al[4][4], bh[2][4], bl[2][4];
#pragma unroll
            for (int mt = 0; mt < 4; mt++) {
                uint32_t aa = base + (arow + mt * 16) * TSTRIDE + (ks * 16 + akc) * 2;
                ldsm4(ah[mt], aa);
                ldsm4(al[mt], aa + TILE_BYTES);
            }
#pragma unroll
            for (int np = 0; np < 2; np++) {
                uint32_t ba = base + 2 * TILE_BYTES + (brow + np * 16) * TSTRIDE + (ks * 16 + bkc) * 2;
                ldsm4(bh[np], ba);
                ldsm4(bl[np], ba + TILE_BYTES);
            }
#pragma unroll
            for (int mt = 0; mt < 4; mt++)
#pragma unroll
                for (int nt = 0; nt < 4; nt++) {
                    const uint32_t* ph = &bh[nt >> 1][(nt & 1) * 2];
                    const uint32_t* pl = &bl[nt >> 1][(nt & 1) * 2];
                    mma16816(acc[mt][nt], ah[mt], ph);
                    mma16816(acc[mt][nt], al[mt], ph);
                    mma16816(acc[mt][nt], ah[mt], pl);
                }
        }
        __syncthreads();
    }

    const int g = lane >> 2, t4 = lane & 3;
#pragma unroll
    for (int mt = 0; mt < 4; mt++)
#pragma unroll
        for (int nt = 0; nt < 4; nt++) {
            int r = m0 + wm + mt * 16 + g;
            int cc = n0 + wn + nt * 8 + t4 * 2;
#pragma unroll
            for (int half = 0; half < 2; half++) {
                int rr = r + half * 8;
                float v0 = acc[mt][nt][half * 2], v1 = acc[mt][nt][half * 2 + 1];
                if (mode == 0) {
                    *(float2*)(C + (size_t)rr * 1024 + cc) = make_float2(v0, v1);
                } else {
                    __nv_bfloat16 b0, b1;
                    if (cc < 1024) {
                        *(float2*)(g_q + (size_t)rr * 1024 + cc) = make_float2(v0, v1);
                        uint32_t hh = pack_hi(v0, v1, b0, b1);
                        *(uint32_t*)(g_qh + (size_t)rr * 1024 + cc) = hh;
                        *(uint32_t*)(g_ql + (size_t)rr * 1024 + cc) =
                            pack_bf16x2(v0 - __bfloat162float(b0), v1 - __bfloat162float(b1));
                    } else if (cc < 1088) {
                        int k = cc - 1024;
                        *(float2*)(g_k + (size_t)rr * 64 + k) = make_float2(v0, v1);
                        uint32_t hh = pack_hi(v0, v1, b0, b1);
                        *(uint32_t*)(g_kh + (size_t)rr * 64 + k) = hh;
                        *(uint32_t*)(g_kl + (size_t)rr * 64 + k) =
                            pack_bf16x2(v0 - __bfloat162float(b0), v1 - __bfloat162float(b1));
                    } else if (cc < 1152) {
                        int k = cc - 1088;
                        *(float2*)(g_v + (size_t)rr * 64 + k) = make_float2(v0, v1);
                        uint32_t hh = pack_hi(v0, v1, b0, b1);
                        *(uint32_t*)(g_vh + (size_t)rr * 64 + k) = hh;
                        *(uint32_t*)(g_vl + (size_t)rr * 64 + k) =
                            pack_bf16x2(v0 - __bfloat162float(b0), v1 - __bfloat162float(b1));
                    } else if (cc < 1200) {
                        int k = cc - 1152;
                        *(float2*)(g_g + (size_t)rr * 48 + k) = make_float2(v0, v1);
                    }
                }
            }
        }
}

// ---------------- mean-pool K,V ---------------------------------------------
__global__ void pool_kv() {
    int c = blockIdx.x, d = threadIdx.x;
    float sk = 0.f, sv = 0.f;
    for (int i = 0; i < 64; i++) {
        sk += g_k[(size_t)(c * 64 + i) * 64 + d];
        sv += g_v[(size_t)(c * 64 + i) * 64 + d];
    }
    g_kc[c * 64 + d] = sk * (1.f / 64.f);
    g_vc[c * 64 + d] = sv * (1.f / 64.f);
}

// ---------------- compressed attention + top-k selection --------------------
__global__ __launch_bounds__(128) void cmp_kernel() {
    __shared__ float sq[1024];
    __shared__ float skc[NB * 64];
    __shared__ float svc[NB * 64];
    __shared__ float sp[NHEAD * NB];
    __shared__ float simp[NB];

    const int t = blockIdx.x, tid = threadIdx.x;
    for (int i = tid; i < 256; i += 128)
        ((float4*)sq)[i] = ((const float4*)(g_q + (size_t)t * 1024))[i];
    for (int i = tid; i < 512; i += 128) {
        ((float4*)skc)[i] = ((const float4*)g_kc)[i];
        ((float4*)svc)[i] = ((const float4*)g_vc)[i];
    }
    __syncthreads();

    const int cur = t >> 6;
    const int nvis = (t + 1) >> 6;
    const float scale = 0.125f;

    for (int idx = tid; idx < NHEAD * NB; idx += 128) {
        int h = idx >> 5, c = idx & 31;
        float s;
        if (c < nvis) {
            const float4* qa = (const float4*)(sq + h * 64);
            const float4* ka = (const float4*)(skc + c * 64);
            s = 0.f;
#pragma unroll
            for (int i = 0; i < 16; i++) {
                float4 x = qa[i], y = ka[i];
                s += x.x * y.x + x.y * y.y + x.z * y.z + x.w * y.w;
            }
            s *= scale;
        } else s = NEGV;
        sp[idx] = s;
    }
    __syncthreads();

    if (tid < NHEAD) {
        float* row = sp + tid * NB;
        if (nvis == 0) {
            for (int c = 0; c < NB; c++) row[c] = 0.f;
        } else {
            float m = -INFINITY;
            for (int c = 0; c < nvis; c++) m = fmaxf(m, row[c]);
            float sum = 0.f;
            for (int c = 0; c < nvis; c++) { float e = __expf(row[c] - m); row[c] = e; sum += e; }
            float inv = 1.f / sum;
            for (int c = 0; c < nvis; c++) row[c] *= inv;
            for (int c = nvis; c < NB; c++) row[c] = 0.f;
        }
    }
    __syncthreads();

    for (int idx = tid; idx < NHEAD * HDIM; idx += 128) {
        int h = idx >> 6, d = idx & 63;
        float o = 0.f;
        for (int c = 0; c < nvis; c++) o += sp[h * NB + c] * svc[c * 64 + d];
        g_ocmp[(size_t)t * 1024 + idx] = o;
    }

    if (tid < NB) {
        int c = tid;
        float im;
        if (c == 0 || c == cur) im = INFINITY;
        else if (c <= cur) {
            im = 0.f;
            for (int h = 0; h < NHEAD; h++) im += sp[h * NB + c];
        } else im = NEGV;
        simp[c] = im;
    }
    __syncthreads();

    // warp-parallel stable top-16 (desc value, lowest index tie-break)
    if (tid < 32) {
        float v = simp[tid];
#pragma unroll
        for (int s = 0; s < SSEL; s++) {
            float bv = v; int bi = tid;
#pragma unroll
            for (int off = 16; off >= 1; off >>= 1) {
                float ov = __shfl_xor_sync(0xffffffffu, bv, off);
                int   oi = __shfl_xor_sync(0xffffffffu, bi, off);
                if (ov > bv || (ov == bv && oi < bi)) { bv = ov; bi = oi; }
            }
            if (tid == 0) g_blk[t * SSEL + s] = bi;
            if (tid == bi) v = -INFINITY;
        }
    }
}

// ============ union-block selected attention, 16 tokens per CTA =============
// smem: sQh 256x144=36864 | sQl +36864 | stages @73728: 2 x {Kh,Kl,Vh,Vl}(9216 ea)
// meta @147456: smask[16], ulist[32], ucount
#define SQL_OFF   36864
#define STG_OFF   73728
#define STG_SZ    36864
#define KV_T      9216
#define META_OFF  147456
#define SLC16_SMEM (147456 + 256)

__global__ __launch_bounds__(256, 1) void slc16() {
    extern __shared__ char smc[];
    const uint32_t sb0 = smem_u32(smc);
    const int tid = threadIdx.x;
    const int lane = tid & 31, w = tid >> 5;
    const int T0 = blockIdx.x * 16;

    uint32_t* smask = (uint32_t*)(smc + META_OFF);
    int* ulist = (int*)(smc + META_OFF + 64);
    int* ucnt  = (int*)(smc + META_OFF + 192);

    // ---- stage Q hi/lo (rows = token*16+head) ----
#pragma unroll
    for (int i = 0; i < 8; i++) {
        int idx = i * 256 + tid;
        int row = idx >> 3, u = idx & 7;
        int token = T0 + (row >> 4), head = row & 15;
        size_t go = (size_t)token * 1024 + head * 64 + u * 8;
        cp_async16(sb0 + row * 144 + u * 16, g_qh + go);
        cp_async16(sb0 + SQL_OFF + row * 144 + u * 16, g_ql + go);
    }
    cp_commit();

    // ---- per-token selection masks + union list ----
    if (tid < 16) {
        uint32_t m = 0;
        for (int s = 0; s < SSEL; s++) m |= 1u << g_blk[(T0 + tid) * SSEL + s];
        smask[tid] = m;
    }
    __syncthreads();
    if (tid == 0) {
        uint32_t u = 0;
        for (int i = 0; i < 16; i++) u |= smask[i];
        int cnt = 0;
        for (int c = 0; c < NB; c++)
            if ((u >> c) & 1u) ulist[cnt++] = c;
        *ucnt = cnt;
    }
    __syncthreads();
    const int nu = *ucnt;

    auto issueKV = [&](int c, int stage) {
        uint32_t base = sb0 + STG_OFF + stage * STG_SZ;
#pragma unroll
        for (int i = 0; i < 8; i++) {
            int cid = i * 256 + tid;
            int tile = cid >> 9, r = (cid >> 3) & 63, u = cid & 7;
            const __nv_bfloat16* gp = (tile == 0) ? g_kh : (tile == 1) ? g_kl
                                    : (tile == 2) ? g_vh : g_vl;
            cp_async16(base + tile * KV_T + r * 144 + u * 16,
                       gp + (size_t)(c * 64 + r) * 64 + u * 8);
        }
        cp_commit();
    };

    issueKV(ulist[0], 0);
    cp_wait1();        // Q group done (stage0 may be pending)
    __syncthreads();

    const uint32_t msk0 = smask[w * 2], msk1 = smask[w * 2 + 1];
    const int tA = T0 + w * 2, tB = tA + 1;

    float ov[2][8][4];
#pragma unroll
    for (int mt = 0; mt < 2; mt++)
#pragma unroll
        for (int vt = 0; vt < 8; vt++)
#pragma unroll
            for (int j = 0; j < 4; j++) ov[mt][vt][j] = 0.f;
    float mrow[2][2] = {{NEGS, NEGS}, {NEGS, NEGS}};
    float srow[2][2] = {{0.f, 0.f}, {0.f, 0.f}};

    for (int i = 0; i < nu; i++) {
        cp_wait0();
        __syncthreads();
        if (i + 1 < nu) issueKV(ulist[i + 1], (i + 1) & 1);

        const int c = ulist[i];
        const bool selA = (msk0 >> c) & 1u, selB = (msk1 >> c) & 1u;
        if (!(selA | selB)) { __syncthreads(); continue; }

        const uint32_t base = sb0 + STG_OFF + (i & 1) * STG_SZ;

        // ---- QK (bf16x3): D[2 tokens][8 ntiles] ----
        float d[2][8][4];
#pragma unroll
        for (int mt = 0; mt < 2; mt++)
#pragma unroll
            for (int nt = 0; nt < 8; nt++)
#pragma unroll
                for (int j = 0; j < 4; j++) d[mt][nt][j] = 0.f;

#pragma unroll
        for (int ks = 0; ks < 4; ks++) {
            uint32_t bh[8][2], bl[8][2];
#pragma unroll
            for (int nt = 0; nt < 8; nt++) {
                uint32_t ba = base + (nt * 8 + (lane & 7)) * 144 + ((lane >> 3) & 1) * 16 + ks * 32;
                ldsm2(bh[nt], ba);
                ldsm2(bl[nt], ba + KV_T);
            }
#pragma unroll
            for (int mt = 0; mt < 2; mt++) {
                uint32_t qa = sb0 + (w * 32 + mt * 16 + (lane & 15)) * 144 + ((lane >> 4) << 4) + ks * 32;
                uint32_t qh4[4], ql4[4];
                ldsm4(qh4, qa);
                ldsm4(ql4, qa + SQL_OFF);
#pragma unroll
                for (int nt = 0; nt < 8; nt++) {
                    mma16816(d[mt][nt], qh4, bh[nt]);
                    mma16816(d[mt][nt], ql4, bh[nt]);
                    mma16816(d[mt][nt], qh4, bl[nt]);
                }
            }
        }

        // ---- scale + mask + online max update ----
        const int colb = c * 64 + ((lane & 3) << 1);
#pragma unroll
        for (int mt = 0; mt < 2; mt++) {
            const bool sel = mt ? selB : selA;
            const int tt = mt ? tB : tA;
            float bm0 = NEGS, bm1 = NEGS;
#pragma unroll
            for (int nt = 0; nt < 8; nt++) {
                int tok0 = colb + nt * 8;
                bool v0 = sel && (tok0 <= tt);
                bool v1 = sel && (tok0 + 1 <= tt);
                d[mt][nt][0] = v0 ? d[mt][nt][0] * 0.125f : NEGS;
                d[mt][nt][1] = v1 ? d[mt][nt][1] * 0.125f : NEGS;
                d[mt][nt][2] = v0 ? d[mt][nt][2] * 0.125f : NEGS;
                d[mt][nt][3] = v1 ? d[mt][nt][3] * 0.125f : NEGS;
                bm0 = fmaxf(bm0, fmaxf(d[mt][nt][0], d[mt][nt][1]));
                bm1 = fmaxf(bm1, fmaxf(d[mt][nt][2], d[mt][nt][3]));
            }
            bm0 = fmaxf(bm0, __shfl_xor_sync(0xffffffffu, bm0, 1));
            bm0 = fmaxf(bm0, __shfl_xor_sync(0xffffffffu, bm0, 2));
            bm1 = fmaxf(bm1, __shfl_xor_sync(0xffffffffu, bm1, 1));
            bm1 = fmaxf(bm1, __shfl_xor_sync(0xffffffffu, bm1, 2));
            float mn0 = fmaxf(mrow[mt][0], bm0), mn1 = fmaxf(mrow[mt][1], bm1);
            float a0 = __expf(mrow[mt][0] - mn0), a1 = __expf(mrow[mt][1] - mn1);
            mrow[mt][0] = mn0; mrow[mt][1] = mn1;
            srow[mt][0] *= a0; srow[mt][1] *= a1;
#pragma unroll
            for (int vt = 0; vt < 8; vt++) {
                ov[mt][vt][0] *= a0; ov[mt][vt][1] *= a0;
                ov[mt][vt][2] *= a1; ov[mt][vt][3] *= a1;
            }
        }

        // ---- exp + PV (bf16x3), V loaded per k-step ----
#pragma unroll
        for (int nt = 0; nt < 8; nt++) {
            uint32_t vh8[8], vl8[8];
            uint32_t va = base + 2 * KV_T + (nt * 8 + (lane & 7)) * 144 + (lane >> 3) * 16;
            ldsm4t(vh8, va);       ldsm4t(vh8 + 4, va + 64);
            ldsm4t(vl8, va + KV_T); ldsm4t(vl8 + 4, va + KV_T + 64);
#pragma unroll
            for (int mt = 0; mt < 2; mt++) {
                float p0 = __expf(d[mt][nt][0] - mrow[mt][0]);
                float p1 = __expf(d[mt][nt][1] - mrow[mt][0]);
                float p2 = __expf(d[mt][nt][2] - mrow[mt][1]);
                float p3 = __expf(d[mt][nt][3] - mrow[mt][1]);
                srow[mt][0] += p0 + p1;
                srow[mt][1] += p2 + p3;
                __nv_bfloat16 b0, b1, b2, b3;
                uint32_t ah0 = pack_hi(p0, p1, b0, b1);
                uint32_t ah1 = pack_hi(p2, p3, b2, b3);
                uint32_t al0 = pack_bf16x2(p0 - __bfloat162float(b0), p1 - __bfloat162float(b1));
                uint32_t al1 = pack_bf16x2(p2 - __bfloat162float(b2), p3 - __bfloat162float(b3));
#pragma unroll
                for (int vt = 0; vt < 8; vt++) {
                    mma16808(ov[mt][vt], ah0, ah1, vh8[vt]);
                    mma16808(ov[mt][vt], al0, al1, vh8[vt]);
                    mma16808(ov[mt][vt], ah0, ah1, vl8[vt]);
                }
            }
        }
        __syncthreads();
    }

    // ---- epilogue: quad-reduce sums, normalize, gate, add ocmp, emit hi/lo ----
#pragma unroll
    for (int mt = 0; mt < 2; mt++) {
        const int tt = mt ? tB : tA;
#pragma unroll
        for (int half = 0; half < 2; half++) {
            float s = srow[mt][half];
            s += __shfl_xor_sync(0xffffffffu, s, 1);
            s += __shfl_xor_sync(0xffffffffu, s, 2);
            float inv = 1.f / s;
            int h = (lane >> 2) + half * 8;
            float gc = 1.f / (1.f + __expf(-g_g[tt * 48 + h * 3]));
            float gs = 1.f / (1.f + __expf(-g_g[tt * 48 + h * 3 + 1]));
#pragma unroll
            for (int vt = 0; vt < 8; vt++) {
                int col = vt * 8 + ((lane & 3) << 1);
                size_t off = (size_t)tt * 1024 + h * 64 + col;
                float2 oc = *(const float2*)(g_ocmp + off);
                float c0 = ov[mt][vt][half * 2]     * inv * gs + oc.x * gc;
                float c1 = ov[mt][vt][half * 2 + 1] * inv * gs + oc.y * gc;
                __nv_bfloat16 b0, b1;
                *(uint32_t*)(g_ch + off) = pack_hi(c0, c1, b0, b1);
                *(uint32_t*)(g_cl + off) =
                    pack_bf16x2(c0 - __bfloat162float(b0), c1 - __bfloat162float(b1));
            }
        }
    }
}

// ---------------- launch ----------------------------------------------------
extern "C" void kernel_launch(void* const* d_in, const int* in_sizes, int n_in,
                              void* d_out, int out_size) {
    const float* x  = (const float*)d_in[0];
    const float* Wq = (const float*)d_in[1];
    const float* Wk = (const float*)d_in[2];
    const float* Wv = (const float*)d_in[3];
    const float* Wg = (const float*)d_in[4];
    const float* Wo = (const float*)d_in[5];
    float* out = (float*)d_out;

    void *pq, *pxh, *pxl, *pch, *pcl, *pwch, *pwcl, *pwoh, *pwol;
    cudaGetSymbolAddress(&pq, g_q);
    cudaGetSymbolAddress(&pxh, g_xh);   cudaGetSymbolAddress(&pxl, g_xl);
    cudaGetSymbolAddress(&pch, g_ch);   cudaGetSymbolAddress(&pcl, g_cl);
    cudaGetSymbolAddress(&pwch, g_wch); cudaGetSymbolAddress(&pwcl, g_wcl);
    cudaGetSymbolAddress(&pwoh, g_woh); cudaGetSymbolAddress(&pwol, g_wol);

    __nv_bfloat16* wch = (__nv_bfloat16*)pwch;
    __nv_bfloat16* wcl = (__nv_bfloat16*)pwcl;

    cudaFuncSetAttribute(gemm_mma, cudaFuncAttributeMaxDynamicSharedMemorySize, GEMM_SMEM);
    cudaFuncSetAttribute(slc16, cudaFuncAttributeMaxDynamicSharedMemorySize, SLC16_SMEM);

    // conversions
    conv_hilo<<<2048, 256>>>((const float4*)x, (uint2*)pxh, (uint2*)pxl, 524288);
    conv_hilo<<<1024, 256>>>((const float4*)Wq, (uint2*)wch, (uint2*)wcl, 262144);
    conv_hilo<<<64, 256>>>((const float4*)Wk, (uint2*)(wch + 1024 * 1024), (uint2*)(wcl + 1024 * 1024), 16384);
    conv_hilo<<<64, 256>>>((const float4*)Wv, (uint2*)(wch + 1088 * 1024), (uint2*)(wcl + 1088 * 1024), 16384);
    conv_hilo<<<48, 256>>>((const float4*)Wg, (uint2*)(wch + 1152 * 1024), (uint2*)(wcl + 1152 * 1024), 12288);
    cudaMemsetAsync(wch + 1200 * 1024, 0, 80 * 1024 * 2);
    cudaMemsetAsync(wcl + 1200 * 1024, 0, 80 * 1024 * 2);
    conv_hilo<<<1024, 256>>>((const float4*)Wo, (uint2*)pwoh, (uint2*)pwol, 262144);

    // fused projections: [Q | K | V | G] = x @ [Wq;Wk;Wv;Wg]^T
    gemm_mma<<<dim3(10, 16), 256, GEMM_SMEM>>>((const __nv_bfloat16*)pxh, (const __nv_bfloat16*)pxl,
                                               wch, wcl, (float*)pq, 1);
    pool_kv<<<NB, 64>>>();
    cmp_kernel<<<T_LEN, 128>>>();
    slc16<<<T_LEN / 16, 256, SLC16_SMEM>>>();

    // out = comb @ Wo^T
    gemm_mma<<<dim3(8, 16), 256, GEMM_SMEM>>>((const __nv_bfloat16*)pch, (const __nv_bfloat16*)pcl,
                                              (const __nv_bfloat16*)pwoh, (const __nv_bfloat16*)pwol,
                                              out, 0);
}

// round 6
// speedup vs baseline: 1.1379x; 1.1379x over previous
#include <cuda_runtime.h>
#include <cuda_bf16.h>
#include <cstdint>

// ---------------- problem constants ----------------
#define T_LEN 2048
#define DM    1024
#define NHEAD 16
#define HDIM  64
#define NB    32
#define SSEL  16
#define NEGV  (-1e30f)
#define NEGS  (-1.25e29f)

// ---------------- scratch ----------------------------------------------------
__device__ float g_q   [T_LEN * DM];
__device__ float g_k   [T_LEN * HDIM];
__device__ float g_v   [T_LEN * HDIM];
__device__ float g_g   [T_LEN * 48];
__device__ float g_kc  [NB * HDIM];
__device__ float g_vc  [NB * HDIM];
__device__ float g_ocmp[T_LEN * DM];
__device__ int   g_blk [T_LEN * SSEL];

__device__ __nv_bfloat16 g_xh [T_LEN * DM], g_xl [T_LEN * DM];
__device__ __nv_bfloat16 g_qh [T_LEN * DM], g_ql [T_LEN * DM];
__device__ __nv_bfloat16 g_ch [T_LEN * DM], g_cl [T_LEN * DM];
__device__ __nv_bfloat16 g_kh [T_LEN * HDIM], g_kl [T_LEN * HDIM];
__device__ __nv_bfloat16 g_vh [T_LEN * HDIM], g_vl [T_LEN * HDIM];
__device__ __nv_bfloat16 g_wch[1280 * DM], g_wcl[1280 * DM];   // stacked Wq|Wk|Wv|Wg|pad
__device__ __nv_bfloat16 g_woh[DM * DM],   g_wol[DM * DM];

// ================= helpers ==================================================
__device__ __forceinline__ uint32_t smem_u32(const void* p) {
    uint32_t a;
    asm("{ .reg .u64 t; cvta.to.shared.u64 t, %1; cvt.u32.u64 %0, t; }"
        : "=r"(a) : "l"(p));
    return a;
}
__device__ __forceinline__ void cp_async16(uint32_t saddr, const void* gaddr) {
    asm volatile("cp.async.cg.shared.global [%0], [%1], 16;"
                 :: "r"(saddr), "l"(gaddr));
}
__device__ __forceinline__ void cp_commit() {
    asm volatile("cp.async.commit_group;" ::: "memory");
}
__device__ __forceinline__ void cp_wait0() {
    asm volatile("cp.async.wait_group 0;" ::: "memory");
}
__device__ __forceinline__ void cp_wait1() {
    asm volatile("cp.async.wait_group 1;" ::: "memory");
}
__device__ __forceinline__ void ldsm4(uint32_t* r, uint32_t addr) {
    asm volatile("ldmatrix.sync.aligned.m8n8.x4.shared.b16 {%0,%1,%2,%3}, [%4];"
                 : "=r"(r[0]), "=r"(r[1]), "=r"(r[2]), "=r"(r[3]) : "r"(addr));
}
__device__ __forceinline__ void ldsm2(uint32_t* r, uint32_t addr) {
    asm volatile("ldmatrix.sync.aligned.m8n8.x2.shared.b16 {%0,%1}, [%2];"
                 : "=r"(r[0]), "=r"(r[1]) : "r"(addr));
}
__device__ __forceinline__ void ldsm4t(uint32_t* r, uint32_t addr) {
    asm volatile("ldmatrix.sync.aligned.m8n8.x4.trans.shared.b16 {%0,%1,%2,%3}, [%4];"
                 : "=r"(r[0]), "=r"(r[1]), "=r"(r[2]), "=r"(r[3]) : "r"(addr));
}
__device__ __forceinline__ void mma16816(float* d, const uint32_t* a, const uint32_t* b) {
    asm volatile(
        "mma.sync.aligned.m16n8k16.row.col.f32.bf16.bf16.f32 "
        "{%0,%1,%2,%3}, {%4,%5,%6,%7}, {%8,%9}, {%0,%1,%2,%3};"
        : "+f"(d[0]), "+f"(d[1]), "+f"(d[2]), "+f"(d[3])
        : "r"(a[0]), "r"(a[1]), "r"(a[2]), "r"(a[3]), "r"(b[0]), "r"(b[1]));
}
__device__ __forceinline__ void mma16808(float* d, uint32_t a0, uint32_t a1, uint32_t b0) {
    asm volatile(
        "mma.sync.aligned.m16n8k8.row.col.f32.bf16.bf16.f32 "
        "{%0,%1,%2,%3}, {%4,%5}, {%6}, {%0,%1,%2,%3};"
        : "+f"(d[0]), "+f"(d[1]), "+f"(d[2]), "+f"(d[3])
        : "r"(a0), "r"(a1), "r"(b0));
}
__device__ __forceinline__ uint32_t pack_bf16x2(float lo, float hi) {
    uint32_t r;
    asm("cvt.rn.bf16x2.f32 %0, %1, %2;" : "=r"(r) : "f"(hi), "f"(lo));
    return r;
}
__device__ __forceinline__ uint32_t pack_hi(float a, float b, __nv_bfloat16& ha, __nv_bfloat16& hb) {
    ha = __float2bfloat16(a); hb = __float2bfloat16(b);
    return (uint32_t)__bfloat16_as_ushort(ha) | ((uint32_t)__bfloat16_as_ushort(hb) << 16);
}

// ================= fp32 -> bf16 hi/lo conversion ============================
__global__ __launch_bounds__(256) void conv_hilo(const float4* __restrict__ src,
                                                 uint2* __restrict__ h,
                                                 uint2* __restrict__ l, int n4) {
    int i = blockIdx.x * 256 + threadIdx.x;
    if (i >= n4) return;
    float4 v = src[i];
    __nv_bfloat16 h0, h1, h2, h3;
    uint32_t a = pack_hi(v.x, v.y, h0, h1);
    uint32_t b = pack_hi(v.z, v.w, h2, h3);
    uint2 hv, lv;
    hv.x = a; hv.y = b;
    lv.x = pack_bf16x2(v.x - __bfloat162float(h0), v.y - __bfloat162float(h1));
    lv.y = pack_bf16x2(v.z - __bfloat162float(h2), v.w - __bfloat162float(h3));
    h[i] = hv;
    l[i] = lv;
}

// ================= tensor-core GEMM via mma.sync (bf16x3) ===================
#define TSTRIDE 80
#define TILE_BYTES (128 * TSTRIDE)
#define BUF_BYTES  (4 * TILE_BYTES)
#define GEMM_SMEM  (2 * BUF_BYTES)

__global__ __launch_bounds__(256) void gemm_mma(const __nv_bfloat16* __restrict__ Ah,
                                                const __nv_bfloat16* __restrict__ Al,
                                                const __nv_bfloat16* __restrict__ Bh,
                                                const __nv_bfloat16* __restrict__ Bl,
                                                float* __restrict__ C,
                                                int mode) {
    extern __shared__ char sm[];
    const uint32_t sbase = smem_u32(sm);
    const int tid = threadIdx.x;
    const int lane = tid & 31, wid = tid >> 5;
    const int m0 = blockIdx.y * 128;
    const int n0 = blockIdx.x * 128;
    const int wm = (wid >> 2) * 64;
    const int wn = (wid & 3) * 32;

    const __nv_bfloat16* gsrc[4] = {Ah, Al, Bh, Bl};

    float acc[4][4][4];
#pragma unroll
    for (int i = 0; i < 4; i++)
#pragma unroll
        for (int j = 0; j < 4; j++)
#pragma unroll
            for (int k = 0; k < 4; k++) acc[i][j][k] = 0.f;

    const int arow = wm + (lane & 15);
    const int akc  = (lane >> 4) << 3;
    const int brow = wn + (lane & 7) + ((lane >> 4) << 3);
    const int bkc  = ((lane >> 3) & 1) << 3;

    auto issue = [&](int c, int buf) {
#pragma unroll
        for (int T = 0; T < 4; T++) {
            const __nv_bfloat16* src = gsrc[T];
            const int rb = (T < 2) ? m0 : n0;
#pragma unroll
            for (int i = 0; i < 2; i++) {
                int idx = i * 256 + tid;
                int row = idx >> 2;
                int u   = idx & 3;
                uint32_t sa = sbase + buf * BUF_BYTES + T * TILE_BYTES + row * TSTRIDE + u * 16;
                cp_async16(sa, src + (size_t)(rb + row) * 1024 + c * 32 + u * 8);
            }
        }
        cp_commit();
    };

    issue(0, 0);

    for (int c = 0; c < 32; c++) {
        const int buf = c & 1;
        cp_wait0();
        __syncthreads();
        if (c + 1 < 32) issue(c + 1, buf ^ 1);

        const uint32_t base = sbase + buf * BUF_BYTES;
#pragma unroll
        for (int ks = 0; ks < 2; ks++) {
            uint32_t ah[4][4], al[4][4], bh[2][4], bl[2][4];
#pragma unroll
            for (int mt = 0; mt < 4; mt++) {
                uint32_t aa = base + (arow + mt * 16) * TSTRIDE + (ks * 16 + akc) * 2;
                ldsm4(ah[mt], aa);
                ldsm4(al[mt], aa + TILE_BYTES);
            }
#pragma unroll
            for (int np = 0; np < 2; np++) {
                uint32_t ba = base + 2 * TILE_BYTES + (brow + np * 16) * TSTRIDE + (ks * 16 + bkc) * 2;
                ldsm4(bh[np], ba);
                ldsm4(bl[np], ba + TILE_BYTES);
            }
#pragma unroll
            for (int mt = 0; mt < 4; mt++)
#pragma unroll
                for (int nt = 0; nt < 4; nt++) {
                    const uint32_t* ph = &bh[nt >> 1][(nt & 1) * 2];
                    const uint32_t* pl = &bl[nt >> 1][(nt & 1) * 2];
                    mma16816(acc[mt][nt], ah[mt], ph);
                    mma16816(acc[mt][nt], al[mt], ph);
                    mma16816(acc[mt][nt], ah[mt], pl);
                }
        }
        __syncthreads();
    }

    const int g = lane >> 2, t4 = lane & 3;
#pragma unroll
    for (int mt = 0; mt < 4; mt++)
#pragma unroll
        for (int nt = 0; nt < 4; nt++) {
            int r = m0 + wm + mt * 16 + g;
            int cc = n0 + wn + nt * 8 + t4 * 2;
#pragma unroll
            for (int half = 0; half < 2; half++) {
                int rr = r + half * 8;
                float v0 = acc[mt][nt][half * 2], v1 = acc[mt][nt][half * 2 + 1];
                if (mode == 0) {
                    *(float2*)(C + (size_t)rr * 1024 + cc) = make_float2(v0, v1);
                } else {
                    __nv_bfloat16 b0, b1;
                    if (cc < 1024) {
                        *(float2*)(g_q + (size_t)rr * 1024 + cc) = make_float2(v0, v1);
                        uint32_t hh = pack_hi(v0, v1, b0, b1);
                        *(uint32_t*)(g_qh + (size_t)rr * 1024 + cc) = hh;
                        *(uint32_t*)(g_ql + (size_t)rr * 1024 + cc) =
                            pack_bf16x2(v0 - __bfloat162float(b0), v1 - __bfloat162float(b1));
                    } else if (cc < 1088) {
                        int k = cc - 1024;
                        *(float2*)(g_k + (size_t)rr * 64 + k) = make_float2(v0, v1);
                        uint32_t hh = pack_hi(v0, v1, b0, b1);
                        *(uint32_t*)(g_kh + (size_t)rr * 64 + k) = hh;
                        *(uint32_t*)(g_kl + (size_t)rr * 64 + k) =
                            pack_bf16x2(v0 - __bfloat162float(b0), v1 - __bfloat162float(b1));
                    } else if (cc < 1152) {
                        int k = cc - 1088;
                        *(float2*)(g_v + (size_t)rr * 64 + k) = make_float2(v0, v1);
                        uint32_t hh = pack_hi(v0, v1, b0, b1);
                        *(uint32_t*)(g_vh + (size_t)rr * 64 + k) = hh;
                        *(uint32_t*)(g_vl + (size_t)rr * 64 + k) =
                            pack_bf16x2(v0 - __bfloat162float(b0), v1 - __bfloat162float(b1));
                    } else if (cc < 1200) {
                        int k = cc - 1152;
                        *(float2*)(g_g + (size_t)rr * 48 + k) = make_float2(v0, v1);
                    }
                }
            }
        }
}

// ---------------- mean-pool K,V ---------------------------------------------
__global__ void pool_kv() {
    int c = blockIdx.x, d = threadIdx.x;
    float sk = 0.f, sv = 0.f;
    for (int i = 0; i < 64; i++) {
        sk += g_k[(size_t)(c * 64 + i) * 64 + d];
        sv += g_v[(size_t)(c * 64 + i) * 64 + d];
    }
    g_kc[c * 64 + d] = sk * (1.f / 64.f);
    g_vc[c * 64 + d] = sv * (1.f / 64.f);
}

// ---------------- compressed attention + top-k selection --------------------
__global__ __launch_bounds__(128) void cmp_kernel() {
    __shared__ float sq[1024];
    __shared__ float skc[NB * 64];
    __shared__ float svc[NB * 64];
    __shared__ float sp[NHEAD * NB];
    __shared__ float simp[NB];

    const int t = blockIdx.x, tid = threadIdx.x;
    for (int i = tid; i < 256; i += 128)
        ((float4*)sq)[i] = ((const float4*)(g_q + (size_t)t * 1024))[i];
    for (int i = tid; i < 512; i += 128) {
        ((float4*)skc)[i] = ((const float4*)g_kc)[i];
        ((float4*)svc)[i] = ((const float4*)g_vc)[i];
    }
    __syncthreads();

    const int cur = t >> 6;
    const int nvis = (t + 1) >> 6;
    const float scale = 0.125f;

    for (int idx = tid; idx < NHEAD * NB; idx += 128) {
        int h = idx >> 5, c = idx & 31;
        float s;
        if (c < nvis) {
            const float4* qa = (const float4*)(sq + h * 64);
            const float4* ka = (const float4*)(skc + c * 64);
            s = 0.f;
#pragma unroll
            for (int i = 0; i < 16; i++) {
                float4 x = qa[i], y = ka[i];
                s += x.x * y.x + x.y * y.y + x.z * y.z + x.w * y.w;
            }
            s *= scale;
        } else s = NEGV;
        sp[idx] = s;
    }
    __syncthreads();

    if (tid < NHEAD) {
        float* row = sp + tid * NB;
        if (nvis == 0) {
            for (int c = 0; c < NB; c++) row[c] = 0.f;
        } else {
            float m = -INFINITY;
            for (int c = 0; c < nvis; c++) m = fmaxf(m, row[c]);
            float sum = 0.f;
            for (int c = 0; c < nvis; c++) { float e = __expf(row[c] - m); row[c] = e; sum += e; }
            float inv = 1.f / sum;
            for (int c = 0; c < nvis; c++) row[c] *= inv;
            for (int c = nvis; c < NB; c++) row[c] = 0.f;
        }
    }
    __syncthreads();

    for (int idx = tid; idx < NHEAD * HDIM; idx += 128) {
        int h = idx >> 6, d = idx & 63;
        float o = 0.f;
        for (int c = 0; c < nvis; c++) o += sp[h * NB + c] * svc[c * 64 + d];
        g_ocmp[(size_t)t * 1024 + idx] = o;
    }

    if (tid < NB) {
        int c = tid;
        float im;
        if (c == 0 || c == cur) im = INFINITY;
        else if (c <= cur) {
            im = 0.f;
            for (int h = 0; h < NHEAD; h++) im += sp[h * NB + c];
        } else im = NEGV;
        simp[c] = im;
    }
    __syncthreads();

    // warp-parallel stable top-16 (desc value, lowest index tie-break)
    if (tid < 32) {
        float v = simp[tid];
#pragma unroll
        for (int s = 0; s < SSEL; s++) {
            float bv = v; int bi = tid;
#pragma unroll
            for (int off = 16; off >= 1; off >>= 1) {
                float ov = __shfl_xor_sync(0xffffffffu, bv, off);
                int   oi = __shfl_xor_sync(0xffffffffu, bi, off);
                if (ov > bv || (ov == bv && oi < bi)) { bv = ov; bi = oi; }
            }
            if (tid == 0) g_blk[t * SSEL + s] = bi;
            if (tid == bi) v = -INFINITY;
        }
    }
}

// ============ union-block selected attention, 16 tokens/CTA, 1 token/warp ===
// 512 threads (16 warps). smem: Qh 256x144 | Ql | 2 KV stages | meta.
#define SQL_OFF   36864
#define STG_OFF   73728
#define STG_SZ    36864
#define KV_T      9216
#define META_OFF  147456
#define SLC16_SMEM (147456 + 256)

__global__ __launch_bounds__(512, 1) void slc16() {
    extern __shared__ char smc[];
    const uint32_t sb0 = smem_u32(smc);
    const int tid = threadIdx.x;
    const int lane = tid & 31, w = tid >> 5;   // w = 0..15, one token per warp
    const int T0 = blockIdx.x * 16;
    const int tt = T0 + w;

    uint32_t* smask = (uint32_t*)(smc + META_OFF);
    int* ulist = (int*)(smc + META_OFF + 64);
    int* ucnt  = (int*)(smc + META_OFF + 192);

    // ---- stage Q hi/lo (row = token*16+head) ----
#pragma unroll
    for (int i = 0; i < 8; i++) {
        int idx = i * 512 + tid;                 // 0..4095
        int tile = idx >> 11;                    // 0 = hi, 1 = lo
        int row = (idx >> 3) & 255, u = idx & 7;
        int token = T0 + (row >> 4), head = row & 15;
        size_t go = (size_t)token * 1024 + head * 64 + u * 8;
        cp_async16(sb0 + tile * SQL_OFF + row * 144 + u * 16, (tile ? g_ql : g_qh) + go);
    }
    cp_commit();

    // ---- per-token selection masks + union list ----
    if (tid < 16) {
        uint32_t m = 0;
        for (int s = 0; s < SSEL; s++) m |= 1u << g_blk[(T0 + tid) * SSEL + s];
        smask[tid] = m;
    }
    __syncthreads();
    if (tid == 0) {
        uint32_t u = 0;
        for (int i = 0; i < 16; i++) u |= smask[i];
        int cnt = 0;
        for (int c = 0; c < NB; c++)
            if ((u >> c) & 1u) ulist[cnt++] = c;
        *ucnt = cnt;
    }
    __syncthreads();
    const int nu = *ucnt;

    auto issueKV = [&](int c, int stage) {
        uint32_t base = sb0 + STG_OFF + stage * STG_SZ;
#pragma unroll
        for (int i = 0; i < 4; i++) {
            int cid = i * 512 + tid;             // 0..2047
            int tile = cid >> 9, r = (cid >> 3) & 63, u = cid & 7;
            const __nv_bfloat16* gp = (tile == 0) ? g_kh : (tile == 1) ? g_kl
                                    : (tile == 2) ? g_vh : g_vl;
            cp_async16(base + tile * KV_T + r * 144 + u * 16,
                       gp + (size_t)(c * 64 + r) * 64 + u * 8);
        }
        cp_commit();
    };

    issueKV(ulist[0], 0);
    cp_wait1();        // Q group complete (KV stage 0 may still be in flight)
    __syncthreads();

    const uint32_t msk = smask[w];

    float ov[8][4];
#pragma unroll
    for (int vt = 0; vt < 8; vt++)
#pragma unroll
        for (int j = 0; j < 4; j++) ov[vt][j] = 0.f;
    float mrow[2] = {NEGS, NEGS};
    float srow[2] = {0.f, 0.f};

    for (int i = 0; i < nu; i++) {
        cp_wait0();
        __syncthreads();
        if (i + 1 < nu) issueKV(ulist[i + 1], (i + 1) & 1);

        const int c = ulist[i];
        if ((msk >> c) & 1u) {
            const uint32_t base = sb0 + STG_OFF + (i & 1) * STG_SZ;

            // ---- QK (bf16x3): D[8 ntiles][4] ----
            float d[8][4];
#pragma unroll
            for (int nt = 0; nt < 8; nt++)
#pragma unroll
                for (int j = 0; j < 4; j++) d[nt][j] = 0.f;

#pragma unroll
            for (int ks = 0; ks < 4; ks++) {
                uint32_t qa = sb0 + (w * 16 + (lane & 15)) * 144 + ((lane >> 4) << 4) + ks * 32;
                uint32_t qh4[4], ql4[4];
                ldsm4(qh4, qa);
                ldsm4(ql4, qa + SQL_OFF);
#pragma unroll
                for (int nt = 0; nt < 8; nt++) {
                    uint32_t bh2[2], bl2[2];
                    uint32_t ba = base + (nt * 8 + (lane & 7)) * 144 + ((lane >> 3) & 1) * 16 + ks * 32;
                    ldsm2(bh2, ba);
                    ldsm2(bl2, ba + KV_T);
                    mma16816(d[nt], qh4, bh2);
                    mma16816(d[nt], ql4, bh2);
                    mma16816(d[nt], qh4, bl2);
                }
            }

            // ---- scale + causal mask + online max/rescale ----
            const int colb = c * 64 + ((lane & 3) << 1);
            float bm0 = NEGS, bm1 = NEGS;
#pragma unroll
            for (int nt = 0; nt < 8; nt++) {
                int tok0 = colb + nt * 8;
                bool v0 = tok0 <= tt, v1 = tok0 + 1 <= tt;
                d[nt][0] = v0 ? d[nt][0] * 0.125f : NEGS;
                d[nt][1] = v1 ? d[nt][1] * 0.125f : NEGS;
                d[nt][2] = v0 ? d[nt][2] * 0.125f : NEGS;
                d[nt][3] = v1 ? d[nt][3] * 0.125f : NEGS;
                bm0 = fmaxf(bm0, fmaxf(d[nt][0], d[nt][1]));
                bm1 = fmaxf(bm1, fmaxf(d[nt][2], d[nt][3]));
            }
            bm0 = fmaxf(bm0, __shfl_xor_sync(0xffffffffu, bm0, 1));
            bm0 = fmaxf(bm0, __shfl_xor_sync(0xffffffffu, bm0, 2));
            bm1 = fmaxf(bm1, __shfl_xor_sync(0xffffffffu, bm1, 1));
            bm1 = fmaxf(bm1, __shfl_xor_sync(0xffffffffu, bm1, 2));
            float mn0 = fmaxf(mrow[0], bm0), mn1 = fmaxf(mrow[1], bm1);
            float a0 = __expf(mrow[0] - mn0), a1 = __expf(mrow[1] - mn1);
            mrow[0] = mn0; mrow[1] = mn1;
            srow[0] *= a0; srow[1] *= a1;
#pragma unroll
            for (int vt = 0; vt < 8; vt++) {
                ov[vt][0] *= a0; ov[vt][1] *= a0;
                ov[vt][2] *= a1; ov[vt][3] *= a1;
            }

            // ---- exp + PV (bf16x3) ----
#pragma unroll
            for (int nt = 0; nt < 8; nt++) {
                uint32_t vh8[8], vl8[8];
                uint32_t va = base + 2 * KV_T + (nt * 8 + (lane & 7)) * 144 + (lane >> 3) * 16;
                ldsm4t(vh8, va);        ldsm4t(vh8 + 4, va + 64);
                ldsm4t(vl8, va + KV_T); ldsm4t(vl8 + 4, va + KV_T + 64);
                float p0 = __expf(d[nt][0] - mrow[0]);
                float p1 = __expf(d[nt][1] - mrow[0]);
                float p2 = __expf(d[nt][2] - mrow[1]);
                float p3 = __expf(d[nt][3] - mrow[1]);
                srow[0] += p0 + p1;
                srow[1] += p2 + p3;
                __nv_bfloat16 b0, b1, b2, b3;
                uint32_t ah0 = pack_hi(p0, p1, b0, b1);
                uint32_t ah1 = pack_hi(p2, p3, b2, b3);
                uint32_t al0 = pack_bf16x2(p0 - __bfloat162float(b0), p1 - __bfloat162float(b1));
                uint32_t al1 = pack_bf16x2(p2 - __bfloat162float(b2), p3 - __bfloat162float(b3));
#pragma unroll
                for (int vt = 0; vt < 8; vt++) {
                    mma16808(ov[vt], ah0, ah1, vh8[vt]);
                    mma16808(ov[vt], al0, al1, vh8[vt]);
                    mma16808(ov[vt], ah0, ah1, vl8[vt]);
                }
            }
        }
        __syncthreads();
    }

    // ---- epilogue: quad-reduce sums, normalize, gate, add ocmp, emit hi/lo ----
#pragma unroll
    for (int half = 0; half < 2; half++) {
        float s = srow[half];
        s += __shfl_xor_sync(0xffffffffu, s, 1);
        s += __shfl_xor_sync(0xffffffffu, s, 2);
        float inv = 1.f / s;
        int h = (lane >> 2) + half * 8;
        float gc = 1.f / (1.f + __expf(-g_g[tt * 48 + h * 3]));
        float gs = 1.f / (1.f + __expf(-g_g[tt * 48 + h * 3 + 1]));
#pragma unroll
        for (int vt = 0; vt < 8; vt++) {
            int col = vt * 8 + ((lane & 3) << 1);
            size_t off = (size_t)tt * 1024 + h * 64 + col;
            float2 oc = *(const float2*)(g_ocmp + off);
            float c0 = ov[vt][half * 2]     * inv * gs + oc.x * gc;
            float c1 = ov[vt][half * 2 + 1] * inv * gs + oc.y * gc;
            __nv_bfloat16 b0, b1;
            *(uint32_t*)(g_ch + off) = pack_hi(c0, c1, b0, b1);
            *(uint32_t*)(g_cl + off) =
                pack_bf16x2(c0 - __bfloat162float(b0), c1 - __bfloat162float(b1));
        }
    }
}

// ---------------- launch ----------------------------------------------------
extern "C" void kernel_launch(void* const* d_in, const int* in_sizes, int n_in,
                              void* d_out, int out_size) {
    const float* x  = (const float*)d_in[0];
    const float* Wq = (const float*)d_in[1];
    const float* Wk = (const float*)d_in[2];
    const float* Wv = (const float*)d_in[3];
    const float* Wg = (const float*)d_in[4];
    const float* Wo = (const float*)d_in[5];
    float* out = (float*)d_out;

    void *pq, *pxh, *pxl, *pch, *pcl, *pwch, *pwcl, *pwoh, *pwol;
    cudaGetSymbolAddress(&pq, g_q);
    cudaGetSymbolAddress(&pxh, g_xh);   cudaGetSymbolAddress(&pxl, g_xl);
    cudaGetSymbolAddress(&pch, g_ch);   cudaGetSymbolAddress(&pcl, g_cl);
    cudaGetSymbolAddress(&pwch, g_wch); cudaGetSymbolAddress(&pwcl, g_wcl);
    cudaGetSymbolAddress(&pwoh, g_woh); cudaGetSymbolAddress(&pwol, g_wol);

    __nv_bfloat16* wch = (__nv_bfloat16*)pwch;
    __nv_bfloat16* wcl = (__nv_bfloat16*)pwcl;

    cudaFuncSetAttribute(gemm_mma, cudaFuncAttributeMaxDynamicSharedMemorySize, GEMM_SMEM);
    cudaFuncSetAttribute(slc16, cudaFuncAttributeMaxDynamicSharedMemorySize, SLC16_SMEM);

    // conversions
    conv_hilo<<<2048, 256>>>((const float4*)x, (uint2*)pxh, (uint2*)pxl, 524288);
    conv_hilo<<<1024, 256>>>((const float4*)Wq, (uint2*)wch, (uint2*)wcl, 262144);
    conv_hilo<<<64, 256>>>((const float4*)Wk, (uint2*)(wch + 1024 * 1024), (uint2*)(wcl + 1024 * 1024), 16384);
    conv_hilo<<<64, 256>>>((const float4*)Wv, (uint2*)(wch + 1088 * 1024), (uint2*)(wcl + 1088 * 1024), 16384);
    conv_hilo<<<48, 256>>>((const float4*)Wg, (uint2*)(wch + 1152 * 1024), (uint2*)(wcl + 1152 * 1024), 12288);
    cudaMemsetAsync(wch + 1200 * 1024, 0, 80 * 1024 * 2);
    cudaMemsetAsync(wcl + 1200 * 1024, 0, 80 * 1024 * 2);
    conv_hilo<<<1024, 256>>>((const float4*)Wo, (uint2*)pwoh, (uint2*)pwol, 262144);

    // fused projections: [Q | K | V | G] = x @ [Wq;Wk;Wv;Wg]^T
    gemm_mma<<<dim3(10, 16), 256, GEMM_SMEM>>>((const __nv_bfloat16*)pxh, (const __nv_bfloat16*)pxl,
                                               wch, wcl, (float*)pq, 1);
    pool_kv<<<NB, 64>>>();
    cmp_kernel<<<T_LEN, 128>>>();
    slc16<<<T_LEN / 16, 512, SLC16_SMEM>>>();

    // out = comb @ Wo^T
    gemm_mma<<<dim3(8, 16), 256, GEMM_SMEM>>>((const __nv_bfloat16*)pch, (const __nv_bfloat16*)pcl,
                                              (const __nv_bfloat16*)pwoh, (const __nv_bfloat16*)pwol,
                                              out, 0);
}